// round 7
// baseline (speedup 1.0000x reference)
#include <cuda_runtime.h>
#include <cuda_bf16.h>
#include <math.h>
#include <cstdint>

#define DD 768
#define LL 256
#define NM 256
#define HH 3072

typedef __nv_bfloat16 bf16;

// ---------------- scratch ----------------
__device__ __align__(16) float g_q[DD];
__device__ __align__(16) float g_qkp[8 * DD];
__device__ __align__(16) float g_pacc[1024 * DD];
__device__ float g_pden[1024];
__device__ __align__(16) float g_xo[NM * DD];
__device__ __align__(16) float g_y[NM * DD];
__device__ __align__(16) float g_h[NM * HH];
__device__ __align__(16) float g_pa[12 * NM * DD];
__device__ __align__(16) float g_pb[3 * NM * HH];
__device__ __align__(16) float g_pc[12 * NM * DD];

// ---------------- helpers ----------------
__device__ __forceinline__ uint32_t smem_u32(const void* p) {
    uint32_t a;
    asm("{ .reg .u64 t; cvta.to.shared.u64 t, %1; cvt.u32.u64 %0, t; }" : "=r"(a) : "l"(p));
    return a;
}
__device__ __forceinline__ unsigned short us(bf16 v) { return __bfloat16_as_ushort(v); }
__device__ __forceinline__ void sp(float a, unsigned short& h, unsigned short& l) {
    bf16 hb = __float2bfloat16_rn(a);
    h = us(hb);
    l = us(__float2bfloat16_rn(a - __bfloat162float(hb)));
}
__device__ __forceinline__ void split2(float v, bf16& h, bf16& l) {
    h = __float2bfloat16_rn(v);
    l = __float2bfloat16_rn(v - __bfloat162float(h));
}
#define SWZ64(o) ((o) ^ (((o) >> 3) & 0x30))

__device__ __forceinline__ void ldsm_x4(uint32_t a[4], uint32_t addr) {
    asm volatile("ldmatrix.sync.aligned.m8n8.x4.shared.b16 {%0,%1,%2,%3}, [%4];"
                 : "=r"(a[0]), "=r"(a[1]), "=r"(a[2]), "=r"(a[3]) : "r"(addr));
}
__device__ __forceinline__ void ldsm_x2(uint32_t a[2], uint32_t addr) {
    asm volatile("ldmatrix.sync.aligned.m8n8.x2.shared.b16 {%0,%1}, [%2];"
                 : "=r"(a[0]), "=r"(a[1]) : "r"(addr));
}
__device__ __forceinline__ void mma16816(float c[4], const uint32_t a[4], const uint32_t b[2]) {
    asm volatile("mma.sync.aligned.m16n8k16.row.col.f32.bf16.bf16.f32 "
                 "{%0,%1,%2,%3}, {%4,%5,%6,%7}, {%8,%9}, {%0,%1,%2,%3};"
                 : "+f"(c[0]), "+f"(c[1]), "+f"(c[2]), "+f"(c[3])
                 : "r"(a[0]), "r"(a[1]), "r"(a[2]), "r"(a[3]), "r"(b[0]), "r"(b[1]));
}

// store 16 fp32 (4x float4) as hi/lo bf16 tiles with SW64 swizzle
__device__ __forceinline__ void stsSplit(bf16* th, bf16* tl, int row, int cg,
                                         const float4 s[4]) {
    unsigned short h[16], l[16];
#pragma unroll
    for (int j = 0; j < 4; j++) {
        sp(s[j].x, h[4 * j + 0], l[4 * j + 0]);
        sp(s[j].y, h[4 * j + 1], l[4 * j + 1]);
        sp(s[j].z, h[4 * j + 2], l[4 * j + 2]);
        sp(s[j].w, h[4 * j + 3], l[4 * j + 3]);
    }
    const uint32_t off = (uint32_t)(row * 64 + cg * 32);
#pragma unroll
    for (int part = 0; part < 2; part++) {
        uint4 H, L;
        H.x = (uint32_t)h[8 * part + 0] | ((uint32_t)h[8 * part + 1] << 16);
        H.y = (uint32_t)h[8 * part + 2] | ((uint32_t)h[8 * part + 3] << 16);
        H.z = (uint32_t)h[8 * part + 4] | ((uint32_t)h[8 * part + 5] << 16);
        H.w = (uint32_t)h[8 * part + 6] | ((uint32_t)h[8 * part + 7] << 16);
        L.x = (uint32_t)l[8 * part + 0] | ((uint32_t)l[8 * part + 1] << 16);
        L.y = (uint32_t)l[8 * part + 2] | ((uint32_t)l[8 * part + 3] << 16);
        L.z = (uint32_t)l[8 * part + 4] | ((uint32_t)l[8 * part + 5] << 16);
        L.w = (uint32_t)l[8 * part + 6] | ((uint32_t)l[8 * part + 7] << 16);
        const uint32_t o = SWZ64(off + part * 16);
        *(uint4*)((char*)th + o) = H;
        *(uint4*)((char*)tl + o) = L;
    }
}

// ---------------- prep: q = probe @ wq^T + bq ----------------
__global__ void __launch_bounds__(256) prep_q(const float* __restrict__ probe,
                                              const float* __restrict__ wq,
                                              const float* __restrict__ bq) {
    __shared__ float spb[DD];
    for (int i = threadIdx.x; i < DD; i += 256) spb[i] = probe[i];
    __syncthreads();
    const int lane = threadIdx.x & 31;
    const int gw = (blockIdx.x * 256 + threadIdx.x) >> 5;
#pragma unroll
    for (int r = 0; r < 4; r++) {
        const int d = gw + r * 192;
        const float4* row = (const float4*)(wq + (size_t)d * DD);
        float s = 0.f;
#pragma unroll
        for (int t = 0; t < 6; t++) {
            float4 w4 = row[lane + 32 * t];
            int e = (lane + 32 * t) * 4;
            s += w4.x * spb[e] + w4.y * spb[e + 1] + w4.z * spb[e + 2] + w4.w * spb[e + 3];
        }
#pragma unroll
        for (int o = 16; o > 0; o >>= 1) s += __shfl_xor_sync(0xffffffffu, s, o);
        if (lane == 0) g_q[d] = s + bq[d];
    }
}

// ---------------- prep: qk partials ----------------
__global__ void __launch_bounds__(256) prep_qk_part(const float* __restrict__ wk) {
    __shared__ float sq[96];
    const int r0 = blockIdx.y * 96;
    if (threadIdx.x < 96) sq[threadIdx.x] = g_q[r0 + threadIdx.x];
    __syncthreads();
    const int col = blockIdx.x * 256 + threadIdx.x;
    const float* wp = wk + (size_t)r0 * DD + col;
    float acc = 0.f;
#pragma unroll 8
    for (int r = 0; r < 96; r++) acc += sq[r] * wp[(size_t)r * DD];
    g_qkp[blockIdx.y * DD + col] = acc * rsqrtf((float)DD);
}

// ---------------- attention pool (proven 5.1 TB/s) ----------------
__global__ void __launch_bounds__(256) attpool(const float* __restrict__ x) {
    __shared__ __align__(16) float sqk[DD];
    __shared__ float sacc[8][DD];
    __shared__ float sden[8];
    const int tid = threadIdx.x, warp = tid >> 5, lane = tid & 31;

    for (int i = tid; i < DD; i += 256) {
        float s = 0.f;
#pragma unroll
        for (int c = 0; c < 8; c++) s += g_qkp[c * DD + i];
        sqk[i] = s;
    }
    __syncthreads();
    const float4* sqk4 = (const float4*)sqk;

    const int pair = blockIdx.x >> 2, quarter = blockIdx.x & 3;
    const float* xp = x + (size_t)pair * (LL * DD) + (size_t)quarter * (64 * DD);

    float4 acc[6];
#pragma unroll
    for (int t = 0; t < 6; t++) acc[t] = make_float4(0.f, 0.f, 0.f, 0.f);
    float den = 0.f;

    float4 xv[2][6];
    {
        const float4* row = (const float4*)(xp + (size_t)warp * DD);
#pragma unroll
        for (int t = 0; t < 6; t++) xv[0][t] = __ldcs(&row[lane + 32 * t]);
    }
#pragma unroll 2
    for (int i = 0; i < 8; i++) {
        const int cur = i & 1;
        if (i + 1 < 8) {
            const float4* row = (const float4*)(xp + (size_t)(warp + (i + 1) * 8) * DD);
#pragma unroll
            for (int t = 0; t < 6; t++) xv[1 - cur][t] = __ldcs(&row[lane + 32 * t]);
        }
        float s = 0.f;
#pragma unroll
        for (int t = 0; t < 6; t++) {
            float4 qv = sqk4[lane + 32 * t];
            s += xv[cur][t].x * qv.x + xv[cur][t].y * qv.y
               + xv[cur][t].z * qv.z + xv[cur][t].w * qv.w;
        }
#pragma unroll
        for (int o = 16; o > 0; o >>= 1) s += __shfl_xor_sync(0xffffffffu, s, o);
        float p = __expf(s);
        den += p;
#pragma unroll
        for (int t = 0; t < 6; t++) {
            acc[t].x += p * xv[cur][t].x;
            acc[t].y += p * xv[cur][t].y;
            acc[t].z += p * xv[cur][t].z;
            acc[t].w += p * xv[cur][t].w;
        }
    }

    if (lane == 0) sden[warp] = den;
    float4* sa4 = (float4*)sacc[warp];
#pragma unroll
    for (int t = 0; t < 6; t++) sa4[lane + 32 * t] = acc[t];
    __syncthreads();

    if (tid == 0) {
        float td = 0.f;
#pragma unroll
        for (int w = 0; w < 8; w++) td += sden[w];
        g_pden[blockIdx.x] = td;
    }
    for (int j = tid; j < DD; j += 256) {
        float s = 0.f;
#pragma unroll
        for (int w = 0; w < 8; w++) s += sacc[w][j];
        g_pacc[(size_t)blockIdx.x * DD + j] = s;
    }
}

// ================= fused split-bf16 HMMA GEMM machinery =================
// CTA tile 128x128, 8 warps (2M x 4N), K-chunk 32 fp32.
// smem: hi/lo tiles for A and B, single-buffered; 3 MMA passes: AhBh+AlBh+AhBl.

struct MmaCtx {
    uint32_t relRowA, cbA0, cbA1, relRowB, cbB0, cbB1;
    int wm, wn, lane;
};
__device__ __forceinline__ MmaCtx mkctx(int tid) {
    MmaCtx c;
    c.lane = tid & 31;
    const int wid = tid >> 5;
    c.wm = wid & 1; c.wn = wid >> 1;
    const uint32_t maskA = (uint32_t)((((c.lane & 15) >> 1) & 3) << 4);
    c.relRowA = (uint32_t)(c.wm * 4096 + (c.lane & 15) * 64);
    c.cbA0 = ((uint32_t)((c.lane >> 4) * 16)) ^ maskA;
    c.cbA1 = ((uint32_t)(32 + (c.lane >> 4) * 16)) ^ maskA;
    const uint32_t maskB = (uint32_t)((((c.lane & 7) >> 1) & 3) << 4);
    c.relRowB = (uint32_t)(c.wn * 2048 + (c.lane & 7) * 64);
    c.cbB0 = ((uint32_t)(((c.lane >> 3) & 1) * 16)) ^ maskB;
    c.cbB1 = ((uint32_t)(32 + ((c.lane >> 3) & 1) * 16)) ^ maskB;
    return c;
}

__device__ __forceinline__ void mma_chunk(float acc[4][4][4], const MmaCtx& cx,
                                          uint32_t aAh, uint32_t aAl,
                                          uint32_t aBh, uint32_t aBl) {
    const uint32_t pa[3] = {aAh + cx.relRowA, aAl + cx.relRowA, aAh + cx.relRowA};
    const uint32_t pb[3] = {aBh + cx.relRowB, aBh + cx.relRowB, aBl + cx.relRowB};
#pragma unroll
    for (int p = 0; p < 3; p++) {
#pragma unroll
        for (int k16 = 0; k16 < 2; k16++) {
            const uint32_t ca = k16 ? cx.cbA1 : cx.cbA0;
            const uint32_t cb = k16 ? cx.cbB1 : cx.cbB0;
            uint32_t af[4][4], bfr[4][2];
#pragma unroll
            for (int mt = 0; mt < 4; mt++) ldsm_x4(af[mt], pa[p] + mt * 1024 + ca);
#pragma unroll
            for (int nt = 0; nt < 4; nt++) ldsm_x2(bfr[nt], pb[p] + nt * 512 + cb);
#pragma unroll
            for (int mt = 0; mt < 4; mt++)
#pragma unroll
                for (int nt = 0; nt < 4; nt++) mma16816(acc[mt][nt], af[mt], bfr[nt]);
        }
    }
}

__device__ __forceinline__ void store_c(float acc[4][4][4], const MmaCtx& cx,
                                        float* C, int m0, int n0, int Nn) {
#pragma unroll
    for (int mt = 0; mt < 4; mt++) {
        const int r = m0 + cx.wm * 64 + mt * 16 + (cx.lane >> 2);
#pragma unroll
        for (int nt = 0; nt < 4; nt++) {
            const int c = n0 + cx.wn * 32 + nt * 8 + (cx.lane & 3) * 2;
            *(float2*)&C[(size_t)r * Nn + c] = make_float2(acc[mt][nt][0], acc[mt][nt][1]);
            *(float2*)&C[(size_t)(r + 8) * Nn + c] = make_float2(acc[mt][nt][2], acc[mt][nt][3]);
        }
    }
}

// generic: A fp32 (M x K row-major), B fp32 (Nn x K row-major)
__global__ void __launch_bounds__(256, 2) fgemm(
    const float* __restrict__ A, const float* __restrict__ B, float* __restrict__ Cbase,
    int K, int kLen, int Nn) {
    __shared__ __align__(16) bf16 smAh[4096], smAl[4096], smBh[4096], smBl[4096];
    const int tid = threadIdx.x;
    const MmaCtx cx = mkctx(tid);
    const int m0 = blockIdx.y * 128, n0 = blockIdx.x * 128;
    const size_t kStart = (size_t)blockIdx.z * kLen;
    float* C = Cbase + (size_t)blockIdx.z * ((size_t)NM * Nn);
    const int nC = kLen / 32;

    const int frow = tid >> 1, fcg = tid & 1;
    const float* gA = A + (size_t)(m0 + frow) * K + kStart + fcg * 16;
    const float* gB = B + (size_t)(n0 + frow) * K + kStart + fcg * 16;

    float4 sA[4], sB[4];
#pragma unroll
    for (int j = 0; j < 4; j++) {
        sA[j] = *(const float4*)(gA + 4 * j);
        sB[j] = *(const float4*)(gB + 4 * j);
    }
    const uint32_t aAh = smem_u32(smAh), aAl = smem_u32(smAl);
    const uint32_t aBh = smem_u32(smBh), aBl = smem_u32(smBl);
    float acc[4][4][4] = {};

    for (int c = 0; c < nC; c++) {
        __syncthreads();
        stsSplit(smAh, smAl, frow, fcg, sA);
        stsSplit(smBh, smBl, frow, fcg, sB);
        if (c + 1 < nC) {
#pragma unroll
            for (int j = 0; j < 4; j++) {
                sA[j] = *(const float4*)(gA + (c + 1) * 32 + 4 * j);
                sB[j] = *(const float4*)(gB + (c + 1) * 32 + 4 * j);
            }
        }
        __syncthreads();
        mma_chunk(acc, cx, aAh, aAl, aBh, aBl);
    }
    store_c(acc, cx, C, m0, n0, Nn);
}

// GEMM A with fused combine: A row m = (sum of 4 attpool quarters) * inv
__global__ void __launch_bounds__(256, 2) fgemm_a(
    const float* __restrict__ B, float* __restrict__ Cbase, int kLen) {
    __shared__ __align__(16) bf16 smAh[4096], smAl[4096], smBh[4096], smBl[4096];
    const int tid = threadIdx.x;
    const MmaCtx cx = mkctx(tid);
    const int m0 = blockIdx.y * 128, n0 = blockIdx.x * 128;
    const size_t kStart = (size_t)blockIdx.z * kLen;
    float* C = Cbase + (size_t)blockIdx.z * ((size_t)NM * DD);
    const int nC = kLen / 32;

    const int frow = tid >> 1, fcg = tid & 1;
    const int mrow = m0 + frow;
    const float inv = 1.0f / (g_pden[4 * mrow] + g_pden[4 * mrow + 1] +
                              g_pden[4 * mrow + 2] + g_pden[4 * mrow + 3]);
    const float* qb = g_pacc + (size_t)(4 * mrow) * DD + kStart + fcg * 16;
    const float* gB = B + (size_t)(n0 + frow) * DD + kStart + fcg * 16;

    auto loadA = [&](int c, float4 s[4]) {
#pragma unroll
        for (int j = 0; j < 4; j++) {
            const float* p = qb + c * 32 + 4 * j;
            float4 q0 = *(const float4*)(p);
            float4 q1 = *(const float4*)(p + DD);
            float4 q2 = *(const float4*)(p + 2 * DD);
            float4 q3 = *(const float4*)(p + 3 * DD);
            s[j] = make_float4((q0.x + q1.x + q2.x + q3.x) * inv,
                               (q0.y + q1.y + q2.y + q3.y) * inv,
                               (q0.z + q1.z + q2.z + q3.z) * inv,
                               (q0.w + q1.w + q2.w + q3.w) * inv);
        }
    };

    float4 sA[4], sB[4];
    loadA(0, sA);
#pragma unroll
    for (int j = 0; j < 4; j++) sB[j] = *(const float4*)(gB + 4 * j);

    const uint32_t aAh = smem_u32(smAh), aAl = smem_u32(smAl);
    const uint32_t aBh = smem_u32(smBh), aBl = smem_u32(smBl);
    float acc[4][4][4] = {};

    for (int c = 0; c < nC; c++) {
        __syncthreads();
        stsSplit(smAh, smAl, frow, fcg, sA);
        stsSplit(smBh, smBl, frow, fcg, sB);
        if (c + 1 < nC) {
            loadA(c + 1, sA);
#pragma unroll
            for (int j = 0; j < 4; j++) sB[j] = *(const float4*)(gB + (c + 1) * 32 + 4 * j);
        }
        __syncthreads();
        mma_chunk(acc, cx, aAh, aAl, aBh, aBl);
    }
    store_c(acc, cx, C, m0, n0, DD);
}

// ---------------- reduce GEMM-A partials (12 slabs) + bias + LN -> y fp32 ----------------
__global__ void __launch_bounds__(256) reduce_ln(const float* __restrict__ bvec,
                                                 const float* __restrict__ gamma,
                                                 const float* __restrict__ beta) {
    const int p = blockIdx.x, tid = threadIdx.x;
    __shared__ float red[256];
    const size_t S = (size_t)NM * DD;
    float xv[3];
    float s = 0.f, ss = 0.f;
#pragma unroll
    for (int r = 0; r < 3; r++) {
        int dcol = tid + r * 256;
        size_t i = (size_t)p * DD + dcol;
        float v = bvec[dcol];
#pragma unroll
        for (int sl = 0; sl < 12; sl++) v += g_pa[sl * S + i];
        g_xo[i] = v;
        xv[r] = v;
        s += v; ss += v * v;
    }
    red[tid] = s; __syncthreads();
    for (int o = 128; o > 0; o >>= 1) { if (tid < o) red[tid] += red[tid + o]; __syncthreads(); }
    float mu = red[0] / (float)DD;
    __syncthreads();
    red[tid] = ss; __syncthreads();
    for (int o = 128; o > 0; o >>= 1) { if (tid < o) red[tid] += red[tid + o]; __syncthreads(); }
    float var = red[0] / (float)DD - mu * mu;
    float rstd = rsqrtf(var + 1e-5f);
#pragma unroll
    for (int r = 0; r < 3; r++) {
        int dcol = tid + r * 256;
        size_t i = (size_t)p * DD + dcol;
        g_y[i] = (xv[r] - mu) * rstd * gamma[dcol] + beta[dcol];
    }
}

// ---------------- reduce GEMM-B partials (3 slabs) + bias + gelu -> h fp32 ----------------
__global__ void __launch_bounds__(256) reduce_gelu(const float* __restrict__ b1) {
    const size_t S = (size_t)NM * HH;
    const size_t base = ((size_t)blockIdx.x * 256 + threadIdx.x) * 4;   // grid 768
    const int col = (int)(base % HH);
    float4 v = *(const float4*)(g_pb + base);
    float4 w1_ = *(const float4*)(g_pb + S + base);
    float4 w2_ = *(const float4*)(g_pb + 2 * S + base);
    float4 bb = *(const float4*)(b1 + col);
    v.x += w1_.x + w2_.x + bb.x; v.y += w1_.y + w2_.y + bb.y;
    v.z += w1_.z + w2_.z + bb.z; v.w += w1_.w + w2_.w + bb.w;
    const float cst = 0.70710678118654752f;
    v.x = 0.5f * v.x * (1.0f + erff(v.x * cst));
    v.y = 0.5f * v.y * (1.0f + erff(v.y * cst));
    v.z = 0.5f * v.z * (1.0f + erff(v.z * cst));
    v.w = 0.5f * v.w * (1.0f + erff(v.w * cst));
    *(float4*)(g_h + base) = v;
}

// ---------------- final: out = xo + (sum 12 GEMM-C slabs) + b2 ----------------
__global__ void __launch_bounds__(256) finalk(const float* __restrict__ b2,
                                              float* __restrict__ out) {
    const size_t S = (size_t)NM * DD;
    const size_t base = ((size_t)blockIdx.x * 256 + threadIdx.x) * 4;   // grid 192
    const int dcol = (int)(base % DD);
    float4 v = *(const float4*)(g_pc + base);
#pragma unroll
    for (int sl = 1; sl < 12; sl++) {
        float4 w = *(const float4*)(g_pc + sl * S + base);
        v.x += w.x; v.y += w.y; v.z += w.z; v.w += w.w;
    }
    float4 xo = *(const float4*)(g_xo + base);
    float4 bb = *(const float4*)(b2 + dcol);
    *(float4*)(out + base) = make_float4(xo.x + v.x + bb.x, xo.y + v.y + bb.y,
                                         xo.z + v.z + bb.z, xo.w + v.w + bb.w);
}

// ---------------- launch ----------------
extern "C" void kernel_launch(void* const* d_in, const int* in_sizes, int n_in,
                              void* d_out, int out_size) {
    const float* x     = (const float*)d_in[0];
    const float* probe = (const float*)d_in[1];
    const float* wq    = (const float*)d_in[2];
    const float* bq    = (const float*)d_in[3];
    const float* wk    = (const float*)d_in[4];
    /* bk unused: constant shift under softmax */
    const float* wv    = (const float*)d_in[6];
    const float* bv    = (const float*)d_in[7];
    const float* gamma = (const float*)d_in[8];
    const float* beta  = (const float*)d_in[9];
    const float* w1    = (const float*)d_in[10];
    const float* b1    = (const float*)d_in[11];
    const float* w2    = (const float*)d_in[12];
    const float* b2    = (const float*)d_in[13];
    float* out = (float*)d_out;

    float *pa, *pb, *pc, *yb, *hb;
    cudaGetSymbolAddress((void**)&pa, g_pa);
    cudaGetSymbolAddress((void**)&pb, g_pb);
    cudaGetSymbolAddress((void**)&pc, g_pc);
    cudaGetSymbolAddress((void**)&yb, g_y);
    cudaGetSymbolAddress((void**)&hb, g_h);

    prep_q<<<24, 256>>>(probe, wq, bq);                           // 1
    prep_qk_part<<<dim3(3, 8), 256>>>(wk);                        // 2
    attpool<<<1024, 256>>>(x);                                    // 3
    fgemm_a<<<dim3(6, 2, 12), 256>>>(wv, pa, 64);                 // 4 <- profiled (144 CTAs)
    reduce_ln<<<NM, 256>>>(bv, gamma, beta);                      // 5
    fgemm<<<dim3(24, 2, 3), 256>>>(yb, w1, pb, DD, 256, HH);      // 6 (144 CTAs)
    reduce_gelu<<<768, 256>>>(b1);                                // 7
    fgemm<<<dim3(6, 2, 12), 256>>>(hb, w2, pc, HH, 256, DD);      // 8 (144 CTAs)
    finalk<<<192, 256>>>(b2, out);                                // 9
}

// round 8
// speedup vs baseline: 1.3582x; 1.3582x over previous
#include <cuda_runtime.h>
#include <cuda_bf16.h>
#include <math.h>
#include <cstdint>

#define DD 768
#define LL 256
#define NM 256
#define HH 3072

typedef __nv_bfloat16 bf16;

// ---------------- scratch ----------------
__device__ __align__(16) float g_q[DD];
__device__ __align__(16) float g_qkp[8 * DD];
__device__ __align__(16) float g_pacc[1024 * DD];
__device__ float g_pden[1024];
__device__ __align__(16) float g_xo[NM * DD];
__device__ __align__(16) float g_y[NM * DD];
__device__ __align__(16) float g_h[NM * HH];
__device__ __align__(16) float g_pa[12 * NM * DD];
__device__ __align__(16) float g_pb[3 * NM * HH];
__device__ __align__(16) float g_pc[12 * NM * DD];

// ---------------- helpers ----------------
__device__ __forceinline__ uint32_t smem_u32(const void* p) {
    uint32_t a;
    asm("{ .reg .u64 t; cvta.to.shared.u64 t, %1; cvt.u32.u64 %0, t; }" : "=r"(a) : "l"(p));
    return a;
}
__device__ __forceinline__ unsigned short us(bf16 v) { return __bfloat16_as_ushort(v); }
__device__ __forceinline__ void sp(float a, unsigned short& h, unsigned short& l) {
    bf16 hb = __float2bfloat16_rn(a);
    h = us(hb);
    l = us(__float2bfloat16_rn(a - __bfloat162float(hb)));
}
#define SWZ64(o) ((o) ^ (((o) >> 3) & 0x30))

__device__ __forceinline__ void ldsm_x4(uint32_t a[4], uint32_t addr) {
    asm volatile("ldmatrix.sync.aligned.m8n8.x4.shared.b16 {%0,%1,%2,%3}, [%4];"
                 : "=r"(a[0]), "=r"(a[1]), "=r"(a[2]), "=r"(a[3]) : "r"(addr));
}
__device__ __forceinline__ void ldsm_x2(uint32_t a[2], uint32_t addr) {
    asm volatile("ldmatrix.sync.aligned.m8n8.x2.shared.b16 {%0,%1}, [%2];"
                 : "=r"(a[0]), "=r"(a[1]) : "r"(addr));
}
__device__ __forceinline__ void mma16816(float c[4], const uint32_t a[4], const uint32_t b[2]) {
    asm volatile("mma.sync.aligned.m16n8k16.row.col.f32.bf16.bf16.f32 "
                 "{%0,%1,%2,%3}, {%4,%5,%6,%7}, {%8,%9}, {%0,%1,%2,%3};"
                 : "+f"(c[0]), "+f"(c[1]), "+f"(c[2]), "+f"(c[3])
                 : "r"(a[0]), "r"(a[1]), "r"(a[2]), "r"(a[3]), "r"(b[0]), "r"(b[1]));
}

// store 8 fp32 (2x float4) as hi/lo bf16 with SW64 swizzle (one uint4 each)
__device__ __forceinline__ void stsSplit8(char* th, char* tl, int row, int cg,
                                          const float4 s[2]) {
    unsigned short h[8], l[8];
    sp(s[0].x, h[0], l[0]); sp(s[0].y, h[1], l[1]);
    sp(s[0].z, h[2], l[2]); sp(s[0].w, h[3], l[3]);
    sp(s[1].x, h[4], l[4]); sp(s[1].y, h[5], l[5]);
    sp(s[1].z, h[6], l[6]); sp(s[1].w, h[7], l[7]);
    uint4 H, L;
    H.x = (uint32_t)h[0] | ((uint32_t)h[1] << 16);
    H.y = (uint32_t)h[2] | ((uint32_t)h[3] << 16);
    H.z = (uint32_t)h[4] | ((uint32_t)h[5] << 16);
    H.w = (uint32_t)h[6] | ((uint32_t)h[7] << 16);
    L.x = (uint32_t)l[0] | ((uint32_t)l[1] << 16);
    L.y = (uint32_t)l[2] | ((uint32_t)l[3] << 16);
    L.z = (uint32_t)l[4] | ((uint32_t)l[5] << 16);
    L.w = (uint32_t)l[6] | ((uint32_t)l[7] << 16);
    const uint32_t o = SWZ64((uint32_t)(row * 64 + cg * 16));
    *(uint4*)(th + o) = H;
    *(uint4*)(tl + o) = L;
}

// ---------------- prep: q = probe @ wq^T + bq ----------------
__global__ void __launch_bounds__(256) prep_q(const float* __restrict__ probe,
                                              const float* __restrict__ wq,
                                              const float* __restrict__ bq) {
    __shared__ float spb[DD];
    for (int i = threadIdx.x; i < DD; i += 256) spb[i] = probe[i];
    __syncthreads();
    const int lane = threadIdx.x & 31;
    const int gw = (blockIdx.x * 256 + threadIdx.x) >> 5;
#pragma unroll
    for (int r = 0; r < 4; r++) {
        const int d = gw + r * 192;
        const float4* row = (const float4*)(wq + (size_t)d * DD);
        float s = 0.f;
#pragma unroll
        for (int t = 0; t < 6; t++) {
            float4 w4 = row[lane + 32 * t];
            int e = (lane + 32 * t) * 4;
            s += w4.x * spb[e] + w4.y * spb[e + 1] + w4.z * spb[e + 2] + w4.w * spb[e + 3];
        }
#pragma unroll
        for (int o = 16; o > 0; o >>= 1) s += __shfl_xor_sync(0xffffffffu, s, o);
        if (lane == 0) g_q[d] = s + bq[d];
    }
}

// ---------------- prep: qk partials ----------------
__global__ void __launch_bounds__(256) prep_qk_part(const float* __restrict__ wk) {
    __shared__ float sq[96];
    const int r0 = blockIdx.y * 96;
    if (threadIdx.x < 96) sq[threadIdx.x] = g_q[r0 + threadIdx.x];
    __syncthreads();
    const int col = blockIdx.x * 256 + threadIdx.x;
    const float* wp = wk + (size_t)r0 * DD + col;
    float acc = 0.f;
#pragma unroll 8
    for (int r = 0; r < 96; r++) acc += sq[r] * wp[(size_t)r * DD];
    g_qkp[blockIdx.y * DD + col] = acc * rsqrtf((float)DD);
}

// ---------------- attention pool (proven 5.1 TB/s) ----------------
__global__ void __launch_bounds__(256) attpool(const float* __restrict__ x) {
    __shared__ __align__(16) float sqk[DD];
    __shared__ float sacc[8][DD];
    __shared__ float sden[8];
    const int tid = threadIdx.x, warp = tid >> 5, lane = tid & 31;

    for (int i = tid; i < DD; i += 256) {
        float s = 0.f;
#pragma unroll
        for (int c = 0; c < 8; c++) s += g_qkp[c * DD + i];
        sqk[i] = s;
    }
    __syncthreads();
    const float4* sqk4 = (const float4*)sqk;

    const int pair = blockIdx.x >> 2, quarter = blockIdx.x & 3;
    const float* xp = x + (size_t)pair * (LL * DD) + (size_t)quarter * (64 * DD);

    float4 acc[6];
#pragma unroll
    for (int t = 0; t < 6; t++) acc[t] = make_float4(0.f, 0.f, 0.f, 0.f);
    float den = 0.f;

    float4 xv[2][6];
    {
        const float4* row = (const float4*)(xp + (size_t)warp * DD);
#pragma unroll
        for (int t = 0; t < 6; t++) xv[0][t] = __ldcs(&row[lane + 32 * t]);
    }
#pragma unroll 2
    for (int i = 0; i < 8; i++) {
        const int cur = i & 1;
        if (i + 1 < 8) {
            const float4* row = (const float4*)(xp + (size_t)(warp + (i + 1) * 8) * DD);
#pragma unroll
            for (int t = 0; t < 6; t++) xv[1 - cur][t] = __ldcs(&row[lane + 32 * t]);
        }
        float s = 0.f;
#pragma unroll
        for (int t = 0; t < 6; t++) {
            float4 qv = sqk4[lane + 32 * t];
            s += xv[cur][t].x * qv.x + xv[cur][t].y * qv.y
               + xv[cur][t].z * qv.z + xv[cur][t].w * qv.w;
        }
#pragma unroll
        for (int o = 16; o > 0; o >>= 1) s += __shfl_xor_sync(0xffffffffu, s, o);
        float p = __expf(s);
        den += p;
#pragma unroll
        for (int t = 0; t < 6; t++) {
            acc[t].x += p * xv[cur][t].x;
            acc[t].y += p * xv[cur][t].y;
            acc[t].z += p * xv[cur][t].z;
            acc[t].w += p * xv[cur][t].w;
        }
    }

    if (lane == 0) sden[warp] = den;
    float4* sa4 = (float4*)sacc[warp];
#pragma unroll
    for (int t = 0; t < 6; t++) sa4[lane + 32 * t] = acc[t];
    __syncthreads();

    if (tid == 0) {
        float td = 0.f;
#pragma unroll
        for (int w = 0; w < 8; w++) td += sden[w];
        g_pden[blockIdx.x] = td;
    }
    for (int j = tid; j < DD; j += 256) {
        float s = 0.f;
#pragma unroll
        for (int w = 0; w < 8; w++) s += sacc[w][j];
        g_pacc[(size_t)blockIdx.x * DD + j] = s;
    }
}

// ================= fused split-bf16 HMMA GEMM, 512 threads =================
// CTA tile 128x128, 16 warps (4M x 4N -> warp 32x32), K-chunk 32 fp32.
// Dynamic smem: 2 buffers x 4 tiles(Ah,Al,Bh,Bl) x 8KB = 64KB. One sync/chunk.
// 3 MMA passes per chunk: AhBh + AlBh + AhBl (AlBl ~ eps^2, dropped).

struct MmaCtx {
    uint32_t relRowA, cbA0, cbA1, relRowB, cbB0, cbB1;
    int wm, wn, lane;
};
__device__ __forceinline__ MmaCtx mkctx(int tid) {
    MmaCtx c;
    c.lane = tid & 31;
    const int wid = tid >> 5;                // 0..15
    c.wm = wid & 3; c.wn = wid >> 2;
    const uint32_t maskA = (uint32_t)((((c.lane & 15) >> 1) & 3) << 4);
    c.relRowA = (uint32_t)(c.wm * 2048 + (c.lane & 15) * 64);
    c.cbA0 = ((uint32_t)((c.lane >> 4) * 16)) ^ maskA;
    c.cbA1 = ((uint32_t)(32 + (c.lane >> 4) * 16)) ^ maskA;
    const uint32_t maskB = (uint32_t)((((c.lane & 7) >> 1) & 3) << 4);
    c.relRowB = (uint32_t)(c.wn * 2048 + (c.lane & 7) * 64);
    c.cbB0 = ((uint32_t)(((c.lane >> 3) & 1) * 16)) ^ maskB;
    c.cbB1 = ((uint32_t)(32 + ((c.lane >> 3) & 1) * 16)) ^ maskB;
    return c;
}

__device__ __forceinline__ void mma_chunk(float acc[2][4][4], const MmaCtx& cx,
                                          uint32_t base) {
    // tiles at base: Ah +0, Al +8192, Bh +16384, Bl +24576
    const uint32_t aAh = base, aAl = base + 8192, aBh = base + 16384, aBl = base + 24576;
    const uint32_t pa[3] = {aAh + cx.relRowA, aAl + cx.relRowA, aAh + cx.relRowA};
    const uint32_t pb[3] = {aBh + cx.relRowB, aBh + cx.relRowB, aBl + cx.relRowB};
#pragma unroll
    for (int p = 0; p < 3; p++) {
#pragma unroll
        for (int k16 = 0; k16 < 2; k16++) {
            const uint32_t ca = k16 ? cx.cbA1 : cx.cbA0;
            const uint32_t cb = k16 ? cx.cbB1 : cx.cbB0;
            uint32_t af[2][4], bfr[4][2];
#pragma unroll
            for (int mt = 0; mt < 2; mt++) ldsm_x4(af[mt], pa[p] + mt * 1024 + ca);
#pragma unroll
            for (int nt = 0; nt < 4; nt++) ldsm_x2(bfr[nt], pb[p] + nt * 512 + cb);
#pragma unroll
            for (int mt = 0; mt < 2; mt++)
#pragma unroll
                for (int nt = 0; nt < 4; nt++) mma16816(acc[mt][nt], af[mt], bfr[nt]);
        }
    }
}

__device__ __forceinline__ void store_c(float acc[2][4][4], const MmaCtx& cx,
                                        float* C, int m0, int n0, int Nn) {
#pragma unroll
    for (int mt = 0; mt < 2; mt++) {
        const int r = m0 + cx.wm * 32 + mt * 16 + (cx.lane >> 2);
#pragma unroll
        for (int nt = 0; nt < 4; nt++) {
            const int c = n0 + cx.wn * 32 + nt * 8 + (cx.lane & 3) * 2;
            *(float2*)&C[(size_t)r * Nn + c] = make_float2(acc[mt][nt][0], acc[mt][nt][1]);
            *(float2*)&C[(size_t)(r + 8) * Nn + c] = make_float2(acc[mt][nt][2], acc[mt][nt][3]);
        }
    }
}

// generic: A fp32 (M x K row-major), B fp32 (Nn x K row-major)
__global__ void __launch_bounds__(512, 1) fgemm(
    const float* __restrict__ A, const float* __restrict__ B, float* __restrict__ Cbase,
    int K, int kLen, int Nn) {
    extern __shared__ __align__(16) char dsm[];
    const int tid = threadIdx.x;
    const MmaCtx cx = mkctx(tid);
    const int m0 = blockIdx.y * 128, n0 = blockIdx.x * 128;
    const size_t kStart = (size_t)blockIdx.z * kLen;
    float* C = Cbase + (size_t)blockIdx.z * ((size_t)NM * Nn);
    const int nC = kLen / 32;

    const int frow = tid >> 2, fcg = tid & 3;     // 128 rows x 4 col-groups of 8 fp32
    const float* gA = A + (size_t)(m0 + frow) * K + kStart + fcg * 8;
    const float* gB = B + (size_t)(n0 + frow) * K + kStart + fcg * 8;
    const uint32_t smb = smem_u32(dsm);

    float4 sA[2], sB[2];
#pragma unroll
    for (int j = 0; j < 2; j++) {
        sA[j] = *(const float4*)(gA + 4 * j);
        sB[j] = *(const float4*)(gB + 4 * j);
    }
    float acc[2][4][4] = {};

    for (int c = 0; c < nC; c++) {
        char* buf = dsm + (size_t)(c & 1) * 32768;
        stsSplit8(buf, buf + 8192, frow, fcg, sA);
        stsSplit8(buf + 16384, buf + 24576, frow, fcg, sB);
        __syncthreads();
        if (c + 1 < nC) {
#pragma unroll
            for (int j = 0; j < 2; j++) {
                sA[j] = *(const float4*)(gA + (c + 1) * 32 + 4 * j);
                sB[j] = *(const float4*)(gB + (c + 1) * 32 + 4 * j);
            }
        }
        mma_chunk(acc, cx, smb + (uint32_t)(c & 1) * 32768);
    }
    store_c(acc, cx, C, m0, n0, Nn);
}

// GEMM A with fused combine: A row m = (sum of 4 attpool quarters) * inv
__global__ void __launch_bounds__(512, 1) fgemm_a(
    const float* __restrict__ B, float* __restrict__ Cbase, int kLen) {
    extern __shared__ __align__(16) char dsm[];
    const int tid = threadIdx.x;
    const MmaCtx cx = mkctx(tid);
    const int m0 = blockIdx.y * 128, n0 = blockIdx.x * 128;
    const size_t kStart = (size_t)blockIdx.z * kLen;
    float* C = Cbase + (size_t)blockIdx.z * ((size_t)NM * DD);
    const int nC = kLen / 32;

    const int frow = tid >> 2, fcg = tid & 3;
    const int mrow = m0 + frow;
    const float inv = 1.0f / (g_pden[4 * mrow] + g_pden[4 * mrow + 1] +
                              g_pden[4 * mrow + 2] + g_pden[4 * mrow + 3]);
    const float* qb = g_pacc + (size_t)(4 * mrow) * DD + kStart + fcg * 8;
    const float* gB = B + (size_t)(n0 + frow) * DD + kStart + fcg * 8;
    const uint32_t smb = smem_u32(dsm);

    auto loadA = [&](int c, float4 s[2]) {
#pragma unroll
        for (int j = 0; j < 2; j++) {
            const float* p = qb + c * 32 + 4 * j;
            float4 q0 = *(const float4*)(p);
            float4 q1 = *(const float4*)(p + DD);
            float4 q2 = *(const float4*)(p + 2 * DD);
            float4 q3 = *(const float4*)(p + 3 * DD);
            s[j] = make_float4((q0.x + q1.x + q2.x + q3.x) * inv,
                               (q0.y + q1.y + q2.y + q3.y) * inv,
                               (q0.z + q1.z + q2.z + q3.z) * inv,
                               (q0.w + q1.w + q2.w + q3.w) * inv);
        }
    };

    float4 sA[2], sB[2];
    loadA(0, sA);
#pragma unroll
    for (int j = 0; j < 2; j++) sB[j] = *(const float4*)(gB + 4 * j);
    float acc[2][4][4] = {};

    for (int c = 0; c < nC; c++) {
        char* buf = dsm + (size_t)(c & 1) * 32768;
        stsSplit8(buf, buf + 8192, frow, fcg, sA);
        stsSplit8(buf + 16384, buf + 24576, frow, fcg, sB);
        __syncthreads();
        if (c + 1 < nC) {
            loadA(c + 1, sA);
#pragma unroll
            for (int j = 0; j < 2; j++) sB[j] = *(const float4*)(gB + (c + 1) * 32 + 4 * j);
        }
        mma_chunk(acc, cx, smb + (uint32_t)(c & 1) * 32768);
    }
    store_c(acc, cx, C, m0, n0, DD);
}

// ---------------- reduce GEMM-A partials (12 slabs) + bias + LN -> y fp32 ----------------
__global__ void __launch_bounds__(256) reduce_ln(const float* __restrict__ bvec,
                                                 const float* __restrict__ gamma,
                                                 const float* __restrict__ beta) {
    const int p = blockIdx.x, tid = threadIdx.x;
    __shared__ float red[256];
    const size_t S = (size_t)NM * DD;
    float xv[3];
    float s = 0.f, ss = 0.f;
#pragma unroll
    for (int r = 0; r < 3; r++) {
        int dcol = tid + r * 256;
        size_t i = (size_t)p * DD + dcol;
        float v = bvec[dcol];
#pragma unroll
        for (int sl = 0; sl < 12; sl++) v += g_pa[sl * S + i];
        g_xo[i] = v;
        xv[r] = v;
        s += v; ss += v * v;
    }
    red[tid] = s; __syncthreads();
    for (int o = 128; o > 0; o >>= 1) { if (tid < o) red[tid] += red[tid + o]; __syncthreads(); }
    float mu = red[0] / (float)DD;
    __syncthreads();
    red[tid] = ss; __syncthreads();
    for (int o = 128; o > 0; o >>= 1) { if (tid < o) red[tid] += red[tid + o]; __syncthreads(); }
    float var = red[0] / (float)DD - mu * mu;
    float rstd = rsqrtf(var + 1e-5f);
#pragma unroll
    for (int r = 0; r < 3; r++) {
        int dcol = tid + r * 256;
        size_t i = (size_t)p * DD + dcol;
        g_y[i] = (xv[r] - mu) * rstd * gamma[dcol] + beta[dcol];
    }
}

// ---------------- reduce GEMM-B partials (3 slabs) + bias + gelu -> h fp32 ----------------
__global__ void __launch_bounds__(256) reduce_gelu(const float* __restrict__ b1) {
    const size_t S = (size_t)NM * HH;
    const size_t base = ((size_t)blockIdx.x * 256 + threadIdx.x) * 4;   // grid 768
    const int col = (int)(base % HH);
    float4 v = *(const float4*)(g_pb + base);
    float4 w1_ = *(const float4*)(g_pb + S + base);
    float4 w2_ = *(const float4*)(g_pb + 2 * S + base);
    float4 bb = *(const float4*)(b1 + col);
    v.x += w1_.x + w2_.x + bb.x; v.y += w1_.y + w2_.y + bb.y;
    v.z += w1_.z + w2_.z + bb.z; v.w += w1_.w + w2_.w + bb.w;
    const float cst = 0.70710678118654752f;
    v.x = 0.5f * v.x * (1.0f + erff(v.x * cst));
    v.y = 0.5f * v.y * (1.0f + erff(v.y * cst));
    v.z = 0.5f * v.z * (1.0f + erff(v.z * cst));
    v.w = 0.5f * v.w * (1.0f + erff(v.w * cst));
    *(float4*)(g_h + base) = v;
}

// ---------------- final: out = xo + (sum 12 GEMM-C slabs) + b2 ----------------
__global__ void __launch_bounds__(256) finalk(const float* __restrict__ b2,
                                              float* __restrict__ out) {
    const size_t S = (size_t)NM * DD;
    const size_t base = ((size_t)blockIdx.x * 256 + threadIdx.x) * 4;   // grid 192
    const int dcol = (int)(base % DD);
    float4 v = *(const float4*)(g_pc + base);
#pragma unroll
    for (int sl = 1; sl < 12; sl++) {
        float4 w = *(const float4*)(g_pc + sl * S + base);
        v.x += w.x; v.y += w.y; v.z += w.z; v.w += w.w;
    }
    float4 xo = *(const float4*)(g_xo + base);
    float4 bb = *(const float4*)(b2 + dcol);
    *(float4*)(out + base) = make_float4(xo.x + v.x + bb.x, xo.y + v.y + bb.y,
                                         xo.z + v.z + bb.z, xo.w + v.w + bb.w);
}

// ---------------- launch ----------------
#define FG_SMEM 65536

extern "C" void kernel_launch(void* const* d_in, const int* in_sizes, int n_in,
                              void* d_out, int out_size) {
    const float* x     = (const float*)d_in[0];
    const float* probe = (const float*)d_in[1];
    const float* wq    = (const float*)d_in[2];
    const float* bq    = (const float*)d_in[3];
    const float* wk    = (const float*)d_in[4];
    /* bk unused: constant shift under softmax */
    const float* wv    = (const float*)d_in[6];
    const float* bv    = (const float*)d_in[7];
    const float* gamma = (const float*)d_in[8];
    const float* beta  = (const float*)d_in[9];
    const float* w1    = (const float*)d_in[10];
    const float* b1    = (const float*)d_in[11];
    const float* w2    = (const float*)d_in[12];
    const float* b2    = (const float*)d_in[13];
    float* out = (float*)d_out;

    cudaFuncSetAttribute(fgemm,   cudaFuncAttributeMaxDynamicSharedMemorySize, FG_SMEM);
    cudaFuncSetAttribute(fgemm_a, cudaFuncAttributeMaxDynamicSharedMemorySize, FG_SMEM);

    float *pa, *pb, *pc, *yb, *hb;
    cudaGetSymbolAddress((void**)&pa, g_pa);
    cudaGetSymbolAddress((void**)&pb, g_pb);
    cudaGetSymbolAddress((void**)&pc, g_pc);
    cudaGetSymbolAddress((void**)&yb, g_y);
    cudaGetSymbolAddress((void**)&hb, g_h);

    prep_q<<<24, 256>>>(probe, wq, bq);                                  // 1
    prep_qk_part<<<dim3(3, 8), 256>>>(wk);                               // 2
    attpool<<<1024, 256>>>(x);                                           // 3
    fgemm_a<<<dim3(6, 2, 12), 512, FG_SMEM>>>(wv, pa, 64);               // 4 <- profiled
    reduce_ln<<<NM, 256>>>(bv, gamma, beta);                             // 5
    fgemm<<<dim3(24, 2, 3), 512, FG_SMEM>>>(yb, w1, pb, DD, 256, HH);    // 6
    reduce_gelu<<<768, 256>>>(b1);                                       // 7
    fgemm<<<dim3(6, 2, 12), 512, FG_SMEM>>>(hb, w2, pc, HH, 256, DD);    // 8
    finalk<<<192, 256>>>(b2, out);                                       // 9
}